// round 5
// baseline (speedup 1.0000x reference)
#include <cuda_runtime.h>
#include <cuda_bf16.h>
#include <cstdint>

// ===========================================================================
// Beam search tree: one bf16 GEMM (mma.sync fallback HMMA, sm_103-safe)
//   Y[B,256] = X[B,128] x W'[256,128]^T,  W' rows interleaved (re_j, im_j).
// 3-term hi/lo split. Persistent CTAs. Software-pipelined:
//   phase A: [epilogue(t-1) on warps 0-3]  ||  [load+convert X(t) on warps 4-15]
//   phase B: GEMM(t) on all 16 warps, then pairwise gain-diffs -> smem
// Gains never staged: pair partner fetched via shfl.xor(1); only 63 diffs/row.
// ===========================================================================

#define GRID    152
#define NTILES  1024            // 131072 rows / 128
#define THREADS 512

#define OFF_XHI 0               // X hi  [128][128] bf16 swizzled (32KB)
#define OFF_XLO 32768           // X lo  (32KB)
#define OFF_WHI 65536           // W hi  [256][128] bf16 (64KB)
#define OFF_WLO 131072          // W lo  (64KB)
#define OFF_DIF 196608          // diffs [64][130] f32 (33280B)
#define DSTR    130
#define SMEM_TOTAL (196608 + 64 * DSTR * 4)   // 229888 <= 232448

typedef unsigned long long u64;

__device__ __host__ __forceinline__ int swz256(int a) { return a ^ ((a >> 4) & 0x70); }

__device__ __forceinline__ uint32_t smem_u32(const void* p) {
    uint32_t a;
    asm("{ .reg .u64 t; cvta.to.shared.u64 t, %1; cvt.u32.u64 %0, t; }" : "=r"(a) : "l"(p));
    return a;
}
#define LDSM4(r, a) \
    asm volatile("ldmatrix.sync.aligned.m8n8.x4.shared.b16 {%0,%1,%2,%3}, [%4];" \
        : "=r"((r)[0]), "=r"((r)[1]), "=r"((r)[2]), "=r"((r)[3]) : "r"(a))

__device__ __forceinline__ void mma_bf16(float* d, const uint32_t* a, uint32_t b0, uint32_t b1) {
    asm volatile("mma.sync.aligned.m16n8k16.row.col.f32.bf16.bf16.f32 "
        "{%0,%1,%2,%3}, {%4,%5,%6,%7}, {%8,%9}, {%0,%1,%2,%3};"
        : "+f"(d[0]), "+f"(d[1]), "+f"(d[2]), "+f"(d[3])
        : "r"(a[0]), "r"(a[1]), "r"(a[2]), "r"(a[3]), "r"(b0), "r"(b1));
}

// ---------------------------------------------------------------------------
// Prep: W' bf16 hi/lo images in final smem layout.
// Row n of W': n=2j -> re coeffs of beam j ([wr | -wi]); n=2j+1 -> im ([wi | wr]).
// ---------------------------------------------------------------------------
__device__ __align__(16) unsigned short g_Whi[32768];
__device__ __align__(16) unsigned short g_Wlo[32768];

__device__ __forceinline__ void store_w(int n, int k, float v) {
    __nv_bfloat16 h = __float2bfloat16(v);
    float l = v - __bfloat162float(h);
    int o = swz256(n * 256 + 2 * k) >> 1;
    g_Whi[o] = __bfloat16_as_ushort(h);
    g_Wlo[o] = __bfloat16_as_ushort(__float2bfloat16(l));
}

__global__ void prep_kernel(const float* __restrict__ t0, const float* __restrict__ t1,
                            const float* __restrict__ t2, const float* __restrict__ t3,
                            const float* __restrict__ t4) {
    int idx = blockIdx.x * blockDim.x + threadIdx.x;
    if (idx >= 64 * 128) return;
    int a = idx >> 7;
    int j = idx & 127;
    float wr = 0.0f, wi = 0.0f;
    if (j < 62) {
        const float* th; int rel;
        if (j < 2)       { th = t0; rel = j; }
        else if (j < 6)  { th = t1; rel = j - 2; }
        else if (j < 14) { th = t2; rel = j - 6; }
        else if (j < 30) { th = t3; rel = j - 14; }
        else             { th = t4; rel = j - 30; }
        int node = rel >> 1, child = rel & 1;
        float theta = th[(node * 64 + a) * 2 + child];
        float s, c;
        sincosf(theta, &s, &c);
        wr = c * 0.125f;  wi = s * 0.125f;
    } else if (j < 126) {
        int jj = j - 62;
        double cmin = cos(3.14159265358979323846 - 1e-6);
        double cj   = 1.0 + (double)jj * ((cmin - 1.0) / 63.0);
        double ph   = 3.14159265358979323846 * (double)a * cj;
        double s, c;
        sincos(ph, &s, &c);
        wr = (float)(c * 0.125);  wi = (float)(s * 0.125);
    }
    store_w(2 * j,     a,      wr);
    store_w(2 * j,     64 + a, -wi);
    store_w(2 * j + 1, a,      wi);
    store_w(2 * j + 1, 64 + a, wr);
}

// ---------------------------------------------------------------------------
// Main persistent kernel
// ---------------------------------------------------------------------------
__global__ void __launch_bounds__(THREADS, 1)
beam_kernel(const float* __restrict__ x, float* __restrict__ out) {
    extern __shared__ char smem[];
    const uint32_t sb = smem_u32(smem);
    float* const dif = (float*)(smem + OFF_DIF);
    const int tid  = threadIdx.x;
    const int lane = tid & 31;
    const int wid  = tid >> 5;
    const int bid  = blockIdx.x;

    // ---- Prologue: stage W hi/lo images (128KB) ----
    {
        float4*       d1 = (float4*)(smem + OFF_WHI);
        const float4* s1 = (const float4*)g_Whi;
        #pragma unroll
        for (int i = tid; i < 4096; i += THREADS) d1[i] = s1[i];
        float4*       d2 = (float4*)(smem + OFF_WLO);
        const float4* s2 = (const float4*)g_Wlo;
        #pragma unroll
        for (int i = tid; i < 4096; i += THREADS) d2[i] = s2[i];
    }

    // Warp tiling: 16 warps = 4(M) x 4(N); warp tile 32 x 64 output cols.
    const int mwarp = wid >> 2, nwarp = wid & 3;
    const int m0 = mwarp * 32, n0 = nwarp * 64;
    const int lrow = lane & 15;
    const int kh2  = (lane >> 4) * 16;
    const int tig  = lane & 3, gid = lane >> 2;

    uint32_t baseA[2], xmA[2], baseBh[4], baseBl[4], xmB[4];
    #pragma unroll
    for (int mb = 0; mb < 2; mb++) {
        int r = m0 + mb * 16 + lrow;
        baseA[mb] = sb + OFF_XHI + (r << 8);
        xmA[mb]   = (r & 7) << 4;
    }
    #pragma unroll
    for (int np = 0; np < 4; np++) {
        int r = n0 + np * 16 + lrow;
        baseBh[np] = sb + OFF_WHI + (r << 8);
        baseBl[np] = sb + OFF_WLO + (r << 8);
        xmB[np]    = (r & 7) << 4;
    }

    const int n_it = (NTILES - 1 - bid) / GRID + 1;

    for (int it = 0; it <= n_it; it++) {
        // ================= phase A: epilogue(it-1) || load(it) =================
        if (tid < 128) {
            if (it > 0) {
                const long ptile = bid + (long)(it - 1) * GRID;
                const int t = tid;
                float rowp[64];
                rowp[0] = 1.0f;
                int qbase = 0, width = 1;
                #pragma unroll
                for (int l = 0; l < 6; l++) {
                    #pragma unroll 32
                    for (int n = width - 1; n >= 0; n--) {
                        int   q  = qbase + n;
                        float p0 = 1.0f / (1.0f + __expf(dif[q * DSTR + t]));
                        float pp = rowp[n];
                        rowp[2 * n]     = pp * p0;
                        rowp[2 * n + 1] = pp - pp * p0;
                    }
                    qbase += width;
                    width <<= 1;
                }
                float4* o4 = (float4*)(out + (ptile * 128 + t) * 64);
                #pragma unroll
                for (int jj = 0; jj < 16; jj++)
                    o4[jj] = make_float4(rowp[4*jj], rowp[4*jj+1], rowp[4*jj+2], rowp[4*jj+3]);
            }
        } else if (it < n_it) {
            const long tile = bid + (long)it * GRID;
            const float4* gx = (const float4*)(x + tile * 16384);
            for (int i4 = tid - 128; i4 < 4096; i4 += 384) {
                float4 v = gx[i4];
                int row = i4 >> 5, c = i4 & 31;
                int boff = swz256(row * 256 + c * 8);
                __nv_bfloat16 h0 = __float2bfloat16(v.x), h1 = __float2bfloat16(v.y);
                __nv_bfloat16 h2 = __float2bfloat16(v.z), h3 = __float2bfloat16(v.w);
                u64 hi = (u64)__bfloat16_as_ushort(h0)
                       | ((u64)__bfloat16_as_ushort(h1) << 16)
                       | ((u64)__bfloat16_as_ushort(h2) << 32)
                       | ((u64)__bfloat16_as_ushort(h3) << 48);
                u64 lo = (u64)__bfloat16_as_ushort(__float2bfloat16(v.x - __bfloat162float(h0)))
                       | ((u64)__bfloat16_as_ushort(__float2bfloat16(v.y - __bfloat162float(h1))) << 16)
                       | ((u64)__bfloat16_as_ushort(__float2bfloat16(v.z - __bfloat162float(h2))) << 32)
                       | ((u64)__bfloat16_as_ushort(__float2bfloat16(v.w - __bfloat162float(h3))) << 48);
                *(u64*)(smem + OFF_XHI + boff) = hi;
                *(u64*)(smem + OFF_XLO + boff) = lo;
            }
        }
        __syncthreads();
        if (it == n_it) break;

        // ================= phase B: GEMM(it) + pair diffs =================
        float acc[2][8][4];
        #pragma unroll
        for (int mb = 0; mb < 2; mb++)
            #pragma unroll
            for (int nb = 0; nb < 8; nb++)
                #pragma unroll
                for (int c = 0; c < 4; c++) acc[mb][nb][c] = 0.0f;

        #pragma unroll
        for (int s = 0; s < 8; s++) {
            const int k2 = 32 * s + kh2;
            uint32_t ah[2][4], al[2][4], bb[4][4];
            #pragma unroll
            for (int mb = 0; mb < 2; mb++) {
                LDSM4(ah[mb], baseA[mb] + (k2 ^ xmA[mb]));
                LDSM4(al[mb], baseA[mb] + 32768 + (k2 ^ xmA[mb]));
            }
            #pragma unroll
            for (int np = 0; np < 4; np++) LDSM4(bb[np], baseBh[np] + (k2 ^ xmB[np]));
            #pragma unroll
            for (int mb = 0; mb < 2; mb++)
                #pragma unroll
                for (int np = 0; np < 4; np++) {
                    mma_bf16(acc[mb][2*np],   ah[mb], bb[np][0], bb[np][2]);
                    mma_bf16(acc[mb][2*np+1], ah[mb], bb[np][1], bb[np][3]);
                    mma_bf16(acc[mb][2*np],   al[mb], bb[np][0], bb[np][2]);
                    mma_bf16(acc[mb][2*np+1], al[mb], bb[np][1], bb[np][3]);
                }
            #pragma unroll
            for (int np = 0; np < 4; np++) LDSM4(bb[np], baseBl[np] + (k2 ^ xmB[np]));
            #pragma unroll
            for (int mb = 0; mb < 2; mb++)
                #pragma unroll
                for (int np = 0; np < 4; np++) {
                    mma_bf16(acc[mb][2*np],   ah[mb], bb[np][0], bb[np][2]);
                    mma_bf16(acc[mb][2*np+1], ah[mb], bb[np][1], bb[np][3]);
                }
        }

        // Pairwise diffs d_q = g(2q+1) - g(2q): partner gain via shfl.xor(1).
        // Fragment c0,c1 = (re,im) of beam j = n0/2 + nb*4 + tig at row m;
        // c2,c3 = same beam at row m+8. tig parity = beam parity.
        #pragma unroll
        for (int mb = 0; mb < 2; mb++)
            #pragma unroll
            for (int nb = 0; nb < 8; nb++) {
                float g0 = acc[mb][nb][0] * acc[mb][nb][0] + acc[mb][nb][1] * acc[mb][nb][1];
                float g1 = acc[mb][nb][2] * acc[mb][nb][2] + acc[mb][nb][3] * acc[mb][nb][3];
                float og0 = __shfl_xor_sync(0xffffffffu, g0, 1);
                float og1 = __shfl_xor_sync(0xffffffffu, g1, 1);
                if ((tig & 1) == 0) {
                    int j = (n0 >> 1) + nb * 4 + tig;   // even beam of the pair (0..126)
                    int q = j >> 1;                     // pair index 0..63
                    int m = m0 + mb * 16 + gid;
                    dif[q * DSTR + m]     = og0 - g0;
                    dif[q * DSTR + m + 8] = og1 - g1;
                }
            }
        __syncthreads();
    }
}

// ---------------------------------------------------------------------------
extern "C" void kernel_launch(void* const* d_in, const int* in_sizes, int n_in,
                              void* d_out, int out_size) {
    const float* x  = (const float*)d_in[0];
    const float* t0 = (const float*)d_in[1];
    const float* t1 = (const float*)d_in[2];
    const float* t2 = (const float*)d_in[3];
    const float* t3 = (const float*)d_in[4];
    const float* t4 = (const float*)d_in[5];
    float* out = (float*)d_out;

    prep_kernel<<<32, 256>>>(t0, t1, t2, t3, t4);

    cudaFuncSetAttribute(beam_kernel, cudaFuncAttributeMaxDynamicSharedMemorySize, SMEM_TOTAL);
    beam_kernel<<<GRID, THREADS, SMEM_TOTAL>>>(x, out);
}

// round 6
// speedup vs baseline: 1.4704x; 1.4704x over previous
#include <cuda_runtime.h>
#include <cuda_bf16.h>
#include <cstdint>

// ===========================================================================
// Beam search tree: one bf16 GEMM (mma.sync fallback HMMA, sm_103-safe)
//   Y[B,256] = X[B,128] x W'[256,128]^T,  W' rows interleaved (re_j, im_j).
// 3-term hi/lo split (xhi*whi + xlo*whi + xhi*wlo). Persistent CTAs.
// Per tile: [load X(t) all threads (unroll-8 MLP) ; epilogue(t-1) all threads]
//           -> sync -> [GEMM pass-structured (indep-16 MMA passes) ; diffs]
// Epilogue: 4 threads/row, one 16-leaf subtree each, reads 63 pair-diffs.
// ===========================================================================

#define GRID    152
#define NTILES  1024            // 131072 rows / 128
#define THREADS 512

#define OFF_XHI 0               // X hi  [128][128] bf16 swizzled (32KB)
#define OFF_XLO 32768           // X lo  (32KB)
#define OFF_WHI 65536           // W hi  [256][128] bf16 (64KB)
#define OFF_WLO 131072          // W lo  (64KB)
#define OFF_DIF 196608          // diffs [64][130] f32 (33280B)
#define DSTR    130
#define SMEM_TOTAL (196608 + 64 * DSTR * 4)   // 229888

typedef unsigned long long u64;

__device__ __host__ __forceinline__ int swz256(int a) { return a ^ ((a >> 4) & 0x70); }

__device__ __forceinline__ uint32_t smem_u32(const void* p) {
    uint32_t a;
    asm("{ .reg .u64 t; cvta.to.shared.u64 t, %1; cvt.u32.u64 %0, t; }" : "=r"(a) : "l"(p));
    return a;
}
#define LDSM4(r, a) \
    asm volatile("ldmatrix.sync.aligned.m8n8.x4.shared.b16 {%0,%1,%2,%3}, [%4];" \
        : "=r"((r)[0]), "=r"((r)[1]), "=r"((r)[2]), "=r"((r)[3]) : "r"(a))

__device__ __forceinline__ void mma_bf16(float* d, const uint32_t* a, uint32_t b0, uint32_t b1) {
    asm volatile("mma.sync.aligned.m16n8k16.row.col.f32.bf16.bf16.f32 "
        "{%0,%1,%2,%3}, {%4,%5,%6,%7}, {%8,%9}, {%0,%1,%2,%3};"
        : "+f"(d[0]), "+f"(d[1]), "+f"(d[2]), "+f"(d[3])
        : "r"(a[0]), "r"(a[1]), "r"(a[2]), "r"(a[3]), "r"(b0), "r"(b1));
}

__device__ __forceinline__ float sigm_neg(float d) {   // 1/(1+exp(d))
    return 1.0f / (1.0f + __expf(d));
}

// ---------------------------------------------------------------------------
// Prep: W' bf16 hi/lo images in final smem layout.
// Row n: n=2j -> re coeffs of beam j ([wr | -wi]); n=2j+1 -> im ([wi | wr]).
// ---------------------------------------------------------------------------
__device__ __align__(16) unsigned short g_Whi[32768];
__device__ __align__(16) unsigned short g_Wlo[32768];

__device__ __forceinline__ void store_w(int n, int k, float v) {
    __nv_bfloat16 h = __float2bfloat16(v);
    float l = v - __bfloat162float(h);
    int o = swz256(n * 256 + 2 * k) >> 1;
    g_Whi[o] = __bfloat16_as_ushort(h);
    g_Wlo[o] = __bfloat16_as_ushort(__float2bfloat16(l));
}

__global__ void prep_kernel(const float* __restrict__ t0, const float* __restrict__ t1,
                            const float* __restrict__ t2, const float* __restrict__ t3,
                            const float* __restrict__ t4) {
    int idx = blockIdx.x * blockDim.x + threadIdx.x;
    if (idx >= 64 * 128) return;
    int a = idx >> 7;
    int j = idx & 127;
    float wr = 0.0f, wi = 0.0f;
    if (j < 62) {
        const float* th; int rel;
        if (j < 2)       { th = t0; rel = j; }
        else if (j < 6)  { th = t1; rel = j - 2; }
        else if (j < 14) { th = t2; rel = j - 6; }
        else if (j < 30) { th = t3; rel = j - 14; }
        else             { th = t4; rel = j - 30; }
        int node = rel >> 1, child = rel & 1;
        float theta = th[(node * 64 + a) * 2 + child];
        float s, c;
        sincosf(theta, &s, &c);
        wr = c * 0.125f;  wi = s * 0.125f;
    } else if (j < 126) {
        int jj = j - 62;
        double cmin = cos(3.14159265358979323846 - 1e-6);
        double cj   = 1.0 + (double)jj * ((cmin - 1.0) / 63.0);
        double ph   = 3.14159265358979323846 * (double)a * cj;
        double s, c;
        sincos(ph, &s, &c);
        wr = (float)(c * 0.125);  wi = (float)(s * 0.125);
    }
    store_w(2 * j,     a,      wr);
    store_w(2 * j,     64 + a, -wi);
    store_w(2 * j + 1, a,      wi);
    store_w(2 * j + 1, 64 + a, wr);
}

// ---------------------------------------------------------------------------
// Main persistent kernel
// ---------------------------------------------------------------------------
__global__ void __launch_bounds__(THREADS, 1)
beam_kernel(const float* __restrict__ x, float* __restrict__ out) {
    extern __shared__ char smem[];
    const uint32_t sb = smem_u32(smem);
    float* const dif = (float*)(smem + OFF_DIF);
    const int tid  = threadIdx.x;
    const int lane = tid & 31;
    const int wid  = tid >> 5;
    const int bid  = blockIdx.x;

    // ---- Prologue: stage W hi/lo images (128KB) ----
    {
        float4*       d1 = (float4*)(smem + OFF_WHI);
        const float4* s1 = (const float4*)g_Whi;
        #pragma unroll
        for (int i = tid; i < 4096; i += THREADS) d1[i] = s1[i];
        float4*       d2 = (float4*)(smem + OFF_WLO);
        const float4* s2 = (const float4*)g_Wlo;
        #pragma unroll
        for (int i = tid; i < 4096; i += THREADS) d2[i] = s2[i];
    }

    // Warp tiling: 16 warps = 4(M) x 4(N); warp tile 32 rows x 64 output cols.
    const int mwarp = wid >> 2, nwarp = wid & 3;
    const int m0 = mwarp * 32, n0 = nwarp * 64;
    const int lrow = lane & 15;
    const int kh2  = (lane >> 4) * 16;
    const int tig  = lane & 3, gid = lane >> 2;

    uint32_t baseA[2], xmA[2], baseBh[4], baseBl[4], xmB[4];
    #pragma unroll
    for (int mb = 0; mb < 2; mb++) {
        int r = m0 + mb * 16 + lrow;
        baseA[mb] = sb + OFF_XHI + (r << 8);
        xmA[mb]   = (r & 7) << 4;
    }
    #pragma unroll
    for (int np = 0; np < 4; np++) {
        int r = n0 + np * 16 + lrow;
        baseBh[np] = sb + OFF_WHI + (r << 8);
        baseBl[np] = sb + OFF_WLO + (r << 8);
        xmB[np]    = (r & 7) << 4;
    }

    const int n_it = (NTILES - 1 - bid) / GRID + 1;

    for (int it = 0; it <= n_it; it++) {
        // ========== phase A: load X(it) then epilogue(it-1), all threads ==========
        if (it < n_it) {
            const long tile = bid + (long)it * GRID;
            const float4* gx = (const float4*)(x + tile * 16384);
            #pragma unroll
            for (int i = 0; i < 8; i++) {
                int i4 = tid + THREADS * i;        // 0..4095
                float4 v = gx[i4];
                int row = i4 >> 5, c = i4 & 31;
                int boff = swz256(row * 256 + c * 8);
                __nv_bfloat16 h0 = __float2bfloat16(v.x), h1 = __float2bfloat16(v.y);
                __nv_bfloat16 h2 = __float2bfloat16(v.z), h3 = __float2bfloat16(v.w);
                u64 hi = (u64)__bfloat16_as_ushort(h0)
                       | ((u64)__bfloat16_as_ushort(h1) << 16)
                       | ((u64)__bfloat16_as_ushort(h2) << 32)
                       | ((u64)__bfloat16_as_ushort(h3) << 48);
                u64 lo = (u64)__bfloat16_as_ushort(__float2bfloat16(v.x - __bfloat162float(h0)))
                       | ((u64)__bfloat16_as_ushort(__float2bfloat16(v.y - __bfloat162float(h1))) << 16)
                       | ((u64)__bfloat16_as_ushort(__float2bfloat16(v.z - __bfloat162float(h2))) << 32)
                       | ((u64)__bfloat16_as_ushort(__float2bfloat16(v.w - __bfloat162float(h3))) << 48);
                *(u64*)(smem + OFF_XHI + boff) = hi;
                *(u64*)(smem + OFF_XLO + boff) = lo;
            }
        }
        if (it > 0) {
            // 4 threads per row; thread handles subtree s (16 leaves).
            const long ptile = bid + (long)(it - 1) * GRID;
            const int row = tid >> 2, s = tid & 3;
            // top chain: level0 q=0, level1 q=1+(s>>1)
            float p0 = sigm_neg(dif[row]);                       // q=0
            float f  = ((s >> 1) == 0) ? p0 : 1.0f - p0;
            p0 = sigm_neg(dif[(1 + (s >> 1)) * DSTR + row]);     // q=1+(s>>1)
            f *= ((s & 1) == 0) ? p0 : 1.0f - p0;
            // level2 node s, q=3+s
            float rp2[2];
            p0 = sigm_neg(dif[(3 + s) * DSTR + row]);
            rp2[0] = f * p0;  rp2[1] = f - f * p0;
            float rp3[4];
            #pragma unroll
            for (int j = 0; j < 2; j++) {
                p0 = sigm_neg(dif[(7 + 2 * s + j) * DSTR + row]);
                rp3[2*j] = rp2[j] * p0;  rp3[2*j+1] = rp2[j] - rp2[j] * p0;
            }
            float rp4[8];
            #pragma unroll
            for (int j = 0; j < 4; j++) {
                p0 = sigm_neg(dif[(15 + 4 * s + j) * DSTR + row]);
                rp4[2*j] = rp3[j] * p0;  rp4[2*j+1] = rp3[j] - rp3[j] * p0;
            }
            float rp5[16];
            #pragma unroll
            for (int j = 0; j < 8; j++) {
                p0 = sigm_neg(dif[(31 + 8 * s + j) * DSTR + row]);
                rp5[2*j] = rp4[j] * p0;  rp5[2*j+1] = rp4[j] - rp4[j] * p0;
            }
            float4* o4 = (float4*)(out + (ptile * 128 + row) * 64 + 16 * s);
            #pragma unroll
            for (int j = 0; j < 4; j++)
                o4[j] = make_float4(rp5[4*j], rp5[4*j+1], rp5[4*j+2], rp5[4*j+3]);
        }
        __syncthreads();
        if (it == n_it) break;

        // ========== phase B: GEMM(it), pass-structured, + pair diffs ==========
        float acc[2][8][4];
        #pragma unroll
        for (int mb = 0; mb < 2; mb++)
            #pragma unroll
            for (int nb = 0; nb < 8; nb++)
                #pragma unroll
                for (int c = 0; c < 4; c++) acc[mb][nb][c] = 0.0f;

        #pragma unroll
        for (int s = 0; s < 8; s++) {
            const int k2 = 32 * s + kh2;
            uint32_t ah[2][4], al[2][4], bh[4][4], bl[4][4];
            #pragma unroll
            for (int mb = 0; mb < 2; mb++) LDSM4(ah[mb], baseA[mb] + (k2 ^ xmA[mb]));
            #pragma unroll
            for (int np = 0; np < 4; np++) LDSM4(bh[np], baseBh[np] + (k2 ^ xmB[np]));
            // pass 1: ah x bh  (16 independent MMAs, all 16 acc targets)
            #pragma unroll
            for (int mb = 0; mb < 2; mb++)
                #pragma unroll
                for (int np = 0; np < 4; np++) {
                    mma_bf16(acc[mb][2*np],   ah[mb], bh[np][0], bh[np][2]);
                    mma_bf16(acc[mb][2*np+1], ah[mb], bh[np][1], bh[np][3]);
                }
            #pragma unroll
            for (int mb = 0; mb < 2; mb++) LDSM4(al[mb], baseA[mb] + 32768 + (k2 ^ xmA[mb]));
            // pass 2: al x bh  (16 independent MMAs)
            #pragma unroll
            for (int mb = 0; mb < 2; mb++)
                #pragma unroll
                for (int np = 0; np < 4; np++) {
                    mma_bf16(acc[mb][2*np],   al[mb], bh[np][0], bh[np][2]);
                    mma_bf16(acc[mb][2*np+1], al[mb], bh[np][1], bh[np][3]);
                }
            #pragma unroll
            for (int np = 0; np < 4; np++) LDSM4(bl[np], baseBl[np] + (k2 ^ xmB[np]));
            // pass 3: ah x bl  (16 independent MMAs)
            #pragma unroll
            for (int mb = 0; mb < 2; mb++)
                #pragma unroll
                for (int np = 0; np < 4; np++) {
                    mma_bf16(acc[mb][2*np],   ah[mb], bl[np][0], bl[np][2]);
                    mma_bf16(acc[mb][2*np+1], ah[mb], bl[np][1], bl[np][3]);
                }
        }

        // Pair diffs d_q = g(2q+1) - g(2q); partner gain via shfl.xor(1).
        #pragma unroll
        for (int mb = 0; mb < 2; mb++)
            #pragma unroll
            for (int nb = 0; nb < 8; nb++) {
                float g0 = acc[mb][nb][0] * acc[mb][nb][0] + acc[mb][nb][1] * acc[mb][nb][1];
                float g1 = acc[mb][nb][2] * acc[mb][nb][2] + acc[mb][nb][3] * acc[mb][nb][3];
                float og0 = __shfl_xor_sync(0xffffffffu, g0, 1);
                float og1 = __shfl_xor_sync(0xffffffffu, g1, 1);
                if ((tig & 1) == 0) {
                    int j = (n0 >> 1) + nb * 4 + tig;   // even beam of the pair
                    int q = j >> 1;                     // pair index 0..63
                    int m = m0 + mb * 16 + gid;
                    dif[q * DSTR + m]     = og0 - g0;
                    dif[q * DSTR + m + 8] = og1 - g1;
                }
            }
        __syncthreads();
    }
}

// ---------------------------------------------------------------------------
extern "C" void kernel_launch(void* const* d_in, const int* in_sizes, int n_in,
                              void* d_out, int out_size) {
    const float* x  = (const float*)d_in[0];
    const float* t0 = (const float*)d_in[1];
    const float* t1 = (const float*)d_in[2];
    const float* t2 = (const float*)d_in[3];
    const float* t3 = (const float*)d_in[4];
    const float* t4 = (const float*)d_in[5];
    float* out = (float*)d_out;

    prep_kernel<<<32, 256>>>(t0, t1, t2, t3, t4);

    cudaFuncSetAttribute(beam_kernel, cudaFuncAttributeMaxDynamicSharedMemorySize, SMEM_TOTAL);
    beam_kernel<<<GRID, THREADS, SMEM_TOTAL>>>(x, out);
}

// round 7
// speedup vs baseline: 1.8445x; 1.2544x over previous
#include <cuda_runtime.h>
#include <cuda_fp16.h>
#include <cstdint>

// ===========================================================================
// Beam search tree: one fp16 GEMM (mma.sync fallback HMMA, sm_103-safe)
//   Y[B,256] = X[B,128] x W'[256,128]^T,  W' rows interleaved (re_j, im_j).
// fp16 2-term split: x = xhi + xlo (two fp16, 22-bit x), w = fp16 (single).
//   y = xhi*w + xlo*w  -> only residual is w quantization (~2^-12).
// Persistent CTAs. Per tile:
//   phase A: 8x LDG.128 -> regs; epilogue(t-1) [hides LDG latency]; cvt+STS
//   phase B: GEMM, 2 passes of 16 independent MMAs per k-step; pair diffs
// Epilogue: 4 threads/row, one 16-leaf subtree each, reads 63 pair-diffs.
// ===========================================================================

#define GRID    152
#define NTILES  1024            // 131072 rows / 128
#define THREADS 512

#define OFF_XHI 0               // X hi  [128][128] fp16 swizzled (32KB)
#define OFF_XLO 32768           // X lo  (32KB)
#define OFF_W   65536           // W     [256][128] fp16 (64KB)
#define OFF_DIF 131072          // diffs [64][130] f32 (33280B)
#define DSTR    130
#define SMEM_TOTAL (131072 + 64 * DSTR * 4)   // 164352

typedef unsigned long long u64;

__device__ __host__ __forceinline__ int swz256(int a) { return a ^ ((a >> 4) & 0x70); }

__device__ __forceinline__ uint32_t smem_u32(const void* p) {
    uint32_t a;
    asm("{ .reg .u64 t; cvta.to.shared.u64 t, %1; cvt.u32.u64 %0, t; }" : "=r"(a) : "l"(p));
    return a;
}
#define LDSM4(r, a) \
    asm volatile("ldmatrix.sync.aligned.m8n8.x4.shared.b16 {%0,%1,%2,%3}, [%4];" \
        : "=r"((r)[0]), "=r"((r)[1]), "=r"((r)[2]), "=r"((r)[3]) : "r"(a))

__device__ __forceinline__ void mma_f16(float* d, const uint32_t* a, uint32_t b0, uint32_t b1) {
    asm volatile("mma.sync.aligned.m16n8k16.row.col.f32.f16.f16.f32 "
        "{%0,%1,%2,%3}, {%4,%5,%6,%7}, {%8,%9}, {%0,%1,%2,%3};"
        : "+f"(d[0]), "+f"(d[1]), "+f"(d[2]), "+f"(d[3])
        : "r"(a[0]), "r"(a[1]), "r"(a[2]), "r"(a[3]), "r"(b0), "r"(b1));
}

__device__ __forceinline__ float sigm_neg(float d) {   // 1/(1+exp(d))
    return 1.0f / (1.0f + __expf(d));
}
__device__ __forceinline__ uint32_t h2raw(__half2 h) {
    return *(uint32_t*)&h;
}

// ---------------------------------------------------------------------------
// Prep: W' fp16 image in final smem layout.
// Row n: n=2j -> re coeffs of beam j ([wr | -wi]); n=2j+1 -> im ([wi | wr]).
// ---------------------------------------------------------------------------
__device__ __align__(16) unsigned short g_W[32768];

__device__ __forceinline__ void store_w(int n, int k, float v) {
    __half h = __float2half(v);
    g_W[swz256(n * 256 + 2 * k) >> 1] = *(unsigned short*)&h;
}

__global__ void prep_kernel(const float* __restrict__ t0, const float* __restrict__ t1,
                            const float* __restrict__ t2, const float* __restrict__ t3,
                            const float* __restrict__ t4) {
    int idx = blockIdx.x * blockDim.x + threadIdx.x;
    if (idx >= 64 * 128) return;
    int a = idx >> 7;
    int j = idx & 127;
    float wr = 0.0f, wi = 0.0f;
    if (j < 62) {
        const float* th; int rel;
        if (j < 2)       { th = t0; rel = j; }
        else if (j < 6)  { th = t1; rel = j - 2; }
        else if (j < 14) { th = t2; rel = j - 6; }
        else if (j < 30) { th = t3; rel = j - 14; }
        else             { th = t4; rel = j - 30; }
        int node = rel >> 1, child = rel & 1;
        float theta = th[(node * 64 + a) * 2 + child];
        float s, c;
        sincosf(theta, &s, &c);
        wr = c * 0.125f;  wi = s * 0.125f;
    } else if (j < 126) {
        int jj = j - 62;
        double cmin = cos(3.14159265358979323846 - 1e-6);
        double cj   = 1.0 + (double)jj * ((cmin - 1.0) / 63.0);
        double ph   = 3.14159265358979323846 * (double)a * cj;
        double s, c;
        sincos(ph, &s, &c);
        wr = (float)(c * 0.125);  wi = (float)(s * 0.125);
    }
    store_w(2 * j,     a,      wr);
    store_w(2 * j,     64 + a, -wi);
    store_w(2 * j + 1, a,      wi);
    store_w(2 * j + 1, 64 + a, wr);
}

// ---------------------------------------------------------------------------
// Main persistent kernel
// ---------------------------------------------------------------------------
__global__ void __launch_bounds__(THREADS, 1)
beam_kernel(const float* __restrict__ x, float* __restrict__ out) {
    extern __shared__ char smem[];
    const uint32_t sb = smem_u32(smem);
    float* const dif = (float*)(smem + OFF_DIF);
    const int tid  = threadIdx.x;
    const int lane = tid & 31;
    const int wid  = tid >> 5;
    const int bid  = blockIdx.x;

    // ---- Prologue: stage W image (64KB) ----
    {
        float4*       d1 = (float4*)(smem + OFF_W);
        const float4* s1 = (const float4*)g_W;
        #pragma unroll
        for (int i = tid; i < 4096; i += THREADS) d1[i] = s1[i];
    }

    // Warp tiling: 16 warps = 4(M) x 4(N); warp tile 32 rows x 64 output cols.
    const int mwarp = wid >> 2, nwarp = wid & 3;
    const int m0 = mwarp * 32, n0 = nwarp * 64;
    const int lrow = lane & 15;
    const int kh2  = (lane >> 4) * 16;
    const int tig  = lane & 3, gid = lane >> 2;

    uint32_t baseA[2], xmA[2], baseB[4], xmB[4];
    #pragma unroll
    for (int mb = 0; mb < 2; mb++) {
        int r = m0 + mb * 16 + lrow;
        baseA[mb] = sb + OFF_XHI + (r << 8);
        xmA[mb]   = (r & 7) << 4;
    }
    #pragma unroll
    for (int np = 0; np < 4; np++) {
        int r = n0 + np * 16 + lrow;
        baseB[np] = sb + OFF_W + (r << 8);
        xmB[np]   = (r & 7) << 4;
    }

    const int n_it = (NTILES - 1 - bid) / GRID + 1;

    for (int it = 0; it <= n_it; it++) {
        // ========== phase A ==========
        // 1) issue all LDGs for tile(it) into registers (latency flies below)
        float4 v[8];
        if (it < n_it) {
            const float4* gx = (const float4*)(x + (bid + (long)it * GRID) * 16384);
            #pragma unroll
            for (int i = 0; i < 8; i++) v[i] = gx[tid + THREADS * i];
        }
        // 2) epilogue(it-1): 4 threads/row, one 16-leaf subtree each
        if (it > 0) {
            const long ptile = bid + (long)(it - 1) * GRID;
            const int row = tid >> 2, s = tid & 3;
            float p0 = sigm_neg(dif[row]);                       // q=0
            float f  = ((s >> 1) == 0) ? p0 : 1.0f - p0;
            p0 = sigm_neg(dif[(1 + (s >> 1)) * DSTR + row]);     // q=1+(s>>1)
            f *= ((s & 1) == 0) ? p0 : 1.0f - p0;
            float rp2[2];
            p0 = sigm_neg(dif[(3 + s) * DSTR + row]);
            rp2[0] = f * p0;  rp2[1] = f - f * p0;
            float rp3[4];
            #pragma unroll
            for (int j = 0; j < 2; j++) {
                p0 = sigm_neg(dif[(7 + 2 * s + j) * DSTR + row]);
                rp3[2*j] = rp2[j] * p0;  rp3[2*j+1] = rp2[j] - rp2[j] * p0;
            }
            float rp4[8];
            #pragma unroll
            for (int j = 0; j < 4; j++) {
                p0 = sigm_neg(dif[(15 + 4 * s + j) * DSTR + row]);
                rp4[2*j] = rp3[j] * p0;  rp4[2*j+1] = rp3[j] - rp3[j] * p0;
            }
            float rp5[16];
            #pragma unroll
            for (int j = 0; j < 8; j++) {
                p0 = sigm_neg(dif[(31 + 8 * s + j) * DSTR + row]);
                rp5[2*j] = rp4[j] * p0;  rp5[2*j+1] = rp4[j] - rp4[j] * p0;
            }
            float4* o4 = (float4*)(out + (ptile * 128 + row) * 64 + 16 * s);
            #pragma unroll
            for (int j = 0; j < 4; j++)
                o4[j] = make_float4(rp5[4*j], rp5[4*j+1], rp5[4*j+2], rp5[4*j+3]);
        }
        // 3) convert + STS (fp16 hi/lo split)
        if (it < n_it) {
            #pragma unroll
            for (int i = 0; i < 8; i++) {
                int i4 = tid + THREADS * i;
                int row = i4 >> 5, c = i4 & 31;
                int boff = swz256(row * 256 + c * 8);
                __half2 h0 = __float22half2_rn(make_float2(v[i].x, v[i].y));
                __half2 h1 = __float22half2_rn(make_float2(v[i].z, v[i].w));
                float2 b0 = __half22float2(h0), b1 = __half22float2(h1);
                __half2 l0 = __float22half2_rn(make_float2(v[i].x - b0.x, v[i].y - b0.y));
                __half2 l1 = __float22half2_rn(make_float2(v[i].z - b1.x, v[i].w - b1.y));
                *(u64*)(smem + OFF_XHI + boff) = (u64)h2raw(h0) | ((u64)h2raw(h1) << 32);
                *(u64*)(smem + OFF_XLO + boff) = (u64)h2raw(l0) | ((u64)h2raw(l1) << 32);
            }
        }
        __syncthreads();
        if (it == n_it) break;

        // ========== phase B: GEMM(it), 2 passes, + pair diffs ==========
        float acc[2][8][4];
        #pragma unroll
        for (int mb = 0; mb < 2; mb++)
            #pragma unroll
            for (int nb = 0; nb < 8; nb++)
                #pragma unroll
                for (int c = 0; c < 4; c++) acc[mb][nb][c] = 0.0f;

        #pragma unroll
        for (int s = 0; s < 8; s++) {
            const int k2 = 32 * s + kh2;
            uint32_t ah[2][4], al[2][4], bh[4][4];
            #pragma unroll
            for (int mb = 0; mb < 2; mb++) LDSM4(ah[mb], baseA[mb] + (k2 ^ xmA[mb]));
            #pragma unroll
            for (int np = 0; np < 4; np++) LDSM4(bh[np], baseB[np] + (k2 ^ xmB[np]));
            // pass 1: xhi x w  (16 independent MMAs)
            #pragma unroll
            for (int mb = 0; mb < 2; mb++)
                #pragma unroll
                for (int np = 0; np < 4; np++) {
                    mma_f16(acc[mb][2*np],   ah[mb], bh[np][0], bh[np][2]);
                    mma_f16(acc[mb][2*np+1], ah[mb], bh[np][1], bh[np][3]);
                }
            #pragma unroll
            for (int mb = 0; mb < 2; mb++) LDSM4(al[mb], baseA[mb] + 32768 + (k2 ^ xmA[mb]));
            // pass 2: xlo x w  (16 independent MMAs)
            #pragma unroll
            for (int mb = 0; mb < 2; mb++)
                #pragma unroll
                for (int np = 0; np < 4; np++) {
                    mma_f16(acc[mb][2*np],   al[mb], bh[np][0], bh[np][2]);
                    mma_f16(acc[mb][2*np+1], al[mb], bh[np][1], bh[np][3]);
                }
        }

        // Pair diffs d_q = g(2q+1) - g(2q); partner gain via shfl.xor(1).
        #pragma unroll
        for (int mb = 0; mb < 2; mb++)
            #pragma unroll
            for (int nb = 0; nb < 8; nb++) {
                float g0 = acc[mb][nb][0] * acc[mb][nb][0] + acc[mb][nb][1] * acc[mb][nb][1];
                float g1 = acc[mb][nb][2] * acc[mb][nb][2] + acc[mb][nb][3] * acc[mb][nb][3];
                float og0 = __shfl_xor_sync(0xffffffffu, g0, 1);
                float og1 = __shfl_xor_sync(0xffffffffu, g1, 1);
                if ((tig & 1) == 0) {
                    int j = (n0 >> 1) + nb * 4 + tig;   // even beam of the pair
                    int q = j >> 1;                     // pair index 0..63
                    int m = m0 + mb * 16 + gid;
                    dif[q * DSTR + m]     = og0 - g0;
                    dif[q * DSTR + m + 8] = og1 - g1;
                }
            }
        __syncthreads();
    }
}

// ---------------------------------------------------------------------------
extern "C" void kernel_launch(void* const* d_in, const int* in_sizes, int n_in,
                              void* d_out, int out_size) {
    const float* x  = (const float*)d_in[0];
    const float* t0 = (const float*)d_in[1];
    const float* t1 = (const float*)d_in[2];
    const float* t2 = (const float*)d_in[3];
    const float* t3 = (const float*)d_in[4];
    const float* t4 = (const float*)d_in[5];
    float* out = (float*)d_out;

    prep_kernel<<<32, 256>>>(t0, t1, t2, t3, t4);

    cudaFuncSetAttribute(beam_kernel, cudaFuncAttributeMaxDynamicSharedMemorySize, SMEM_TOTAL);
    beam_kernel<<<GRID, THREADS, SMEM_TOTAL>>>(x, out);
}

// round 8
// speedup vs baseline: 1.8756x; 1.0168x over previous
#include <cuda_runtime.h>
#include <cuda_fp16.h>
#include <cstdint>

// ===========================================================================
// Beam search tree: one fp16 GEMM (mma.sync fallback HMMA, sm_103-safe)
//   Y[B,256] = X[B,128] x W'[256,128]^T,  W' rows interleaved (re_j, im_j).
// fp16 2-term split: x = xhi + xlo, w = fp16. Residual ~2^-12 (w quant).
// NOW: 2 CTAs / SM (256 thr, 64-row tiles) so one CTA's GEMM phase overlaps
// the other CTA's load/epilogue phase. Same math as the 79us kernel.
// ===========================================================================

#define GRID    304
#define NTILES  2048            // 131072 rows / 64
#define THREADS 256
#define MROWS   64

#define OFF_XHI 0               // X hi  [64][128] fp16 swizzled (16KB)
#define OFF_XLO 16384           // X lo  (16KB)
#define OFF_W   32768           // W     [256][128] fp16 (64KB)
#define OFF_DIF 98304           // diffs [64][65] f32 (16640B)
#define DSTR    65
#define SMEM_TOTAL (98304 + 64 * DSTR * 4)   // 114944 -> 2 CTAs/SM

typedef unsigned long long u64;

__device__ __host__ __forceinline__ int swz256(int a) { return a ^ ((a >> 4) & 0x70); }

__device__ __forceinline__ uint32_t smem_u32(const void* p) {
    uint32_t a;
    asm("{ .reg .u64 t; cvta.to.shared.u64 t, %1; cvt.u32.u64 %0, t; }" : "=r"(a) : "l"(p));
    return a;
}
#define LDSM4(r, a) \
    asm volatile("ldmatrix.sync.aligned.m8n8.x4.shared.b16 {%0,%1,%2,%3}, [%4];" \
        : "=r"((r)[0]), "=r"((r)[1]), "=r"((r)[2]), "=r"((r)[3]) : "r"(a))

__device__ __forceinline__ void mma_f16(float* d, const uint32_t* a, uint32_t b0, uint32_t b1) {
    asm volatile("mma.sync.aligned.m16n8k16.row.col.f32.f16.f16.f32 "
        "{%0,%1,%2,%3}, {%4,%5,%6,%7}, {%8,%9}, {%0,%1,%2,%3};"
        : "+f"(d[0]), "+f"(d[1]), "+f"(d[2]), "+f"(d[3])
        : "r"(a[0]), "r"(a[1]), "r"(a[2]), "r"(a[3]), "r"(b0), "r"(b1));
}

__device__ __forceinline__ float sigm_neg(float d) {   // 1/(1+exp(d))
    return 1.0f / (1.0f + __expf(d));
}
__device__ __forceinline__ uint32_t h2raw(__half2 h) {
    return *(uint32_t*)&h;
}

// ---------------------------------------------------------------------------
// Prep: W' fp16 image in final smem layout.
// Row n: n=2j -> re coeffs of beam j ([wr | -wi]); n=2j+1 -> im ([wi | wr]).
// ---------------------------------------------------------------------------
__device__ __align__(16) unsigned short g_W[32768];

__device__ __forceinline__ void store_w(int n, int k, float v) {
    __half h = __float2half(v);
    g_W[swz256(n * 256 + 2 * k) >> 1] = *(unsigned short*)&h;
}

__global__ void prep_kernel(const float* __restrict__ t0, const float* __restrict__ t1,
                            const float* __restrict__ t2, const float* __restrict__ t3,
                            const float* __restrict__ t4) {
    int idx = blockIdx.x * blockDim.x + threadIdx.x;
    if (idx >= 64 * 128) return;
    int a = idx >> 7;
    int j = idx & 127;
    float wr = 0.0f, wi = 0.0f;
    if (j < 62) {
        const float* th; int rel;
        if (j < 2)       { th = t0; rel = j; }
        else if (j < 6)  { th = t1; rel = j - 2; }
        else if (j < 14) { th = t2; rel = j - 6; }
        else if (j < 30) { th = t3; rel = j - 14; }
        else             { th = t4; rel = j - 30; }
        int node = rel >> 1, child = rel & 1;
        float theta = th[(node * 64 + a) * 2 + child];
        float s, c;
        sincosf(theta, &s, &c);
        wr = c * 0.125f;  wi = s * 0.125f;
    } else if (j < 126) {
        int jj = j - 62;
        double cmin = cos(3.14159265358979323846 - 1e-6);
        double cj   = 1.0 + (double)jj * ((cmin - 1.0) / 63.0);
        double ph   = 3.14159265358979323846 * (double)a * cj;
        double s, c;
        sincos(ph, &s, &c);
        wr = (float)(c * 0.125);  wi = (float)(s * 0.125);
    }
    store_w(2 * j,     a,      wr);
    store_w(2 * j,     64 + a, -wi);
    store_w(2 * j + 1, a,      wi);
    store_w(2 * j + 1, 64 + a, wr);
}

// ---------------------------------------------------------------------------
// Main persistent kernel: 8 warps = 2(M) x 4(N), warp tile 32 rows x 64 cols.
// ---------------------------------------------------------------------------
__global__ void __launch_bounds__(THREADS, 2)
beam_kernel(const float* __restrict__ x, float* __restrict__ out) {
    extern __shared__ char smem[];
    const uint32_t sb = smem_u32(smem);
    float* const dif = (float*)(smem + OFF_DIF);
    const int tid  = threadIdx.x;
    const int lane = tid & 31;
    const int wid  = tid >> 5;
    const int bid  = blockIdx.x;

    // ---- Prologue: stage W image (64KB) ----
    {
        float4*       d1 = (float4*)(smem + OFF_W);
        const float4* s1 = (const float4*)g_W;
        #pragma unroll
        for (int i = tid; i < 4096; i += THREADS) d1[i] = s1[i];
    }

    const int mwarp = wid >> 2, nwarp = wid & 3;    // 2 x 4 warp grid
    const int m0 = mwarp * 32, n0 = nwarp * 64;
    const int lrow = lane & 15;
    const int kh2  = (lane >> 4) * 16;
    const int tig  = lane & 3, gid = lane >> 2;

    uint32_t baseA[2], xmA[2], baseB[4], xmB[4];
    #pragma unroll
    for (int mb = 0; mb < 2; mb++) {
        int r = m0 + mb * 16 + lrow;
        baseA[mb] = sb + OFF_XHI + (r << 8);
        xmA[mb]   = (r & 7) << 4;
    }
    #pragma unroll
    for (int np = 0; np < 4; np++) {
        int r = n0 + np * 16 + lrow;
        baseB[np] = sb + OFF_W + (r << 8);
        xmB[np]   = (r & 7) << 4;
    }

    const int n_it = (NTILES - 1 - bid) / GRID + 1;

    for (int it = 0; it <= n_it; it++) {
        // ========== phase A ==========
        // 1) issue all LDGs for tile(it) into registers
        float4 v[8];
        if (it < n_it) {
            const float4* gx = (const float4*)(x + (bid + (long)it * GRID) * 8192);
            #pragma unroll
            for (int i = 0; i < 8; i++) v[i] = gx[tid + THREADS * i];
        }
        // 2) epilogue(it-1): 4 threads/row, one 16-leaf subtree each
        if (it > 0) {
            const long ptile = bid + (long)(it - 1) * GRID;
            const int row = tid >> 2, s = tid & 3;
            float p0 = sigm_neg(dif[row]);                       // q=0
            float f  = ((s >> 1) == 0) ? p0 : 1.0f - p0;
            p0 = sigm_neg(dif[(1 + (s >> 1)) * DSTR + row]);     // q=1+(s>>1)
            f *= ((s & 1) == 0) ? p0 : 1.0f - p0;
            float rp2[2];
            p0 = sigm_neg(dif[(3 + s) * DSTR + row]);
            rp2[0] = f * p0;  rp2[1] = f - f * p0;
            float rp3[4];
            #pragma unroll
            for (int j = 0; j < 2; j++) {
                p0 = sigm_neg(dif[(7 + 2 * s + j) * DSTR + row]);
                rp3[2*j] = rp2[j] * p0;  rp3[2*j+1] = rp2[j] - rp2[j] * p0;
            }
            float rp4[8];
            #pragma unroll
            for (int j = 0; j < 4; j++) {
                p0 = sigm_neg(dif[(15 + 4 * s + j) * DSTR + row]);
                rp4[2*j] = rp3[j] * p0;  rp4[2*j+1] = rp3[j] - rp3[j] * p0;
            }
            float rp5[16];
            #pragma unroll
            for (int j = 0; j < 8; j++) {
                p0 = sigm_neg(dif[(31 + 8 * s + j) * DSTR + row]);
                rp5[2*j] = rp4[j] * p0;  rp5[2*j+1] = rp4[j] - rp4[j] * p0;
            }
            float4* o4 = (float4*)(out + (ptile * MROWS + row) * 64 + 16 * s);
            #pragma unroll
            for (int j = 0; j < 4; j++)
                o4[j] = make_float4(rp5[4*j], rp5[4*j+1], rp5[4*j+2], rp5[4*j+3]);
        }
        // 3) convert + STS (fp16 hi/lo split)
        if (it < n_it) {
            #pragma unroll
            for (int i = 0; i < 8; i++) {
                int i4 = tid + THREADS * i;        // 0..2047
                int row = i4 >> 5, c = i4 & 31;
                int boff = swz256(row * 256 + c * 8);
                __half2 h0 = __float22half2_rn(make_float2(v[i].x, v[i].y));
                __half2 h1 = __float22half2_rn(make_float2(v[i].z, v[i].w));
                float2 b0 = __half22float2(h0), b1 = __half22float2(h1);
                __half2 l0 = __float22half2_rn(make_float2(v[i].x - b0.x, v[i].y - b0.y));
                __half2 l1 = __float22half2_rn(make_float2(v[i].z - b1.x, v[i].w - b1.y));
                *(u64*)(smem + OFF_XHI + boff) = (u64)h2raw(h0) | ((u64)h2raw(h1) << 32);
                *(u64*)(smem + OFF_XLO + boff) = (u64)h2raw(l0) | ((u64)h2raw(l1) << 32);
            }
        }
        __syncthreads();
        if (it == n_it) break;

        // ========== phase B: GEMM(it), 2 passes, + pair diffs ==========
        float acc[2][8][4];
        #pragma unroll
        for (int mb = 0; mb < 2; mb++)
            #pragma unroll
            for (int nb = 0; nb < 8; nb++)
                #pragma unroll
                for (int c = 0; c < 4; c++) acc[mb][nb][c] = 0.0f;

        #pragma unroll
        for (int s = 0; s < 8; s++) {
            const int k2 = 32 * s + kh2;
            uint32_t ah[2][4], al[2][4], bh[4][4];
            #pragma unroll
            for (int mb = 0; mb < 2; mb++) LDSM4(ah[mb], baseA[mb] + (k2 ^ xmA[mb]));
            #pragma unroll
            for (int np = 0; np < 4; np++) LDSM4(bh[np], baseB[np] + (k2 ^ xmB[np]));
            // pass 1: xhi x w
            #pragma unroll
            for (int mb = 0; mb < 2; mb++)
                #pragma unroll
                for (int np = 0; np < 4; np++) {
                    mma_f16(acc[mb][2*np],   ah[mb], bh[np][0], bh[np][2]);
                    mma_f16(acc[mb][2*np+1], ah[mb], bh[np][1], bh[np][3]);
                }
            #pragma unroll
            for (int mb = 0; mb < 2; mb++) LDSM4(al[mb], baseA[mb] + 16384 + (k2 ^ xmA[mb]));
            // pass 2: xlo x w
            #pragma unroll
            for (int mb = 0; mb < 2; mb++)
                #pragma unroll
                for (int np = 0; np < 4; np++) {
                    mma_f16(acc[mb][2*np],   al[mb], bh[np][0], bh[np][2]);
                    mma_f16(acc[mb][2*np+1], al[mb], bh[np][1], bh[np][3]);
                }
        }

        // Pair diffs d_q = g(2q+1) - g(2q); partner gain via shfl.xor(1).
        #pragma unroll
        for (int mb = 0; mb < 2; mb++)
            #pragma unroll
            for (int nb = 0; nb < 8; nb++) {
                float g0 = acc[mb][nb][0] * acc[mb][nb][0] + acc[mb][nb][1] * acc[mb][nb][1];
                float g1 = acc[mb][nb][2] * acc[mb][nb][2] + acc[mb][nb][3] * acc[mb][nb][3];
                float og0 = __shfl_xor_sync(0xffffffffu, g0, 1);
                float og1 = __shfl_xor_sync(0xffffffffu, g1, 1);
                if ((tig & 1) == 0) {
                    int j = (n0 >> 1) + nb * 4 + tig;   // even beam of the pair
                    int q = j >> 1;                     // pair index 0..63
                    int m = m0 + mb * 16 + gid;
                    dif[q * DSTR + m]     = og0 - g0;
                    dif[q * DSTR + m + 8] = og1 - g1;
                }
            }
        __syncthreads();
    }
}

// ---------------------------------------------------------------------------
extern "C" void kernel_launch(void* const* d_in, const int* in_sizes, int n_in,
                              void* d_out, int out_size) {
    const float* x  = (const float*)d_in[0];
    const float* t0 = (const float*)d_in[1];
    const float* t1 = (const float*)d_in[2];
    const float* t2 = (const float*)d_in[3];
    const float* t3 = (const float*)d_in[4];
    const float* t4 = (const float*)d_in[5];
    float* out = (float*)d_out;

    prep_kernel<<<32, 256>>>(t0, t1, t2, t3, t4);

    cudaFuncSetAttribute(beam_kernel, cudaFuncAttributeMaxDynamicSharedMemorySize, SMEM_TOTAL);
    beam_kernel<<<GRID, THREADS, SMEM_TOTAL>>>(x, out);
}